// round 13
// baseline (speedup 1.0000x reference)
#include <cuda_runtime.h>
#include <cuda_bf16.h>
#include <math.h>
#include <stdint.h>

#define NTOK 2048
#define DIM  1024
#define HEADS 16
#define HEADD 64
#define FFNH 4096
#define LE   8
#define TOPK 2
#define DIME 512
#define DIMS 1024
#define NASSIGN (NTOK*TOPK)
#define MAXTILES 40

typedef unsigned short u16;

// ---------------- weight split arena offsets (elements) ----------------
#define OFF_DAW  0LL
#define OFF_DAO  6291456LL
#define OFF_DUP  8388608LL
#define OFF_DDN  25165824LL
#define OFF_MAW  33554432LL
#define OFF_MAO  39845888LL
#define OFF_W12  41943040LL   /* interleaved W1|W2: 2 layers x 8 experts x 1024x1024 */
#define OFF_W3   58720256LL
#define OFF_MSUP 67108864LL
#define OFF_MSDN 71303168LL
#define WTOTAL   73400320LL

// ---------------- scratch (device globals; no allocation) ----------------
__device__ __align__(16) u16 g_wh[WTOTAL];
__device__ __align__(16) u16 g_wl[WTOTAL];
__device__ __align__(16) u16 g_sxnh[NTOK*DIM],   g_sxnl[NTOK*DIM];
__device__ __align__(16) u16 g_satth[NTOK*DIM],  g_sattl[NTOK*DIM];
__device__ __align__(16) u16 g_shh[NTOK*FFNH],   g_shl[NTOK*FFNH];
__device__ __align__(16) u16 g_sxph[NASSIGN*DIM],g_sxpl[NASSIGN*DIM];
__device__ __align__(16) u16 g_shsh[NASSIGN*DIME],g_shsl[NASSIGN*DIME];

__device__ __align__(16) float g_xn [NTOK*DIM];
__device__ __align__(16) float g_qkv[NTOK*3*DIM];
__device__ __align__(16) float g_xi [NTOK*DIM];
__device__ __align__(16) float g_yp [NASSIGN*DIM];
__device__ __align__(16) float g_tv [NTOK*LE];
__device__ __align__(16) float g_sc [NTOK*TOPK];
__device__ __align__(16) float g_xa [NTOK*DIM];
__device__ __align__(16) float g_xb [NTOK*DIM];
__device__ int g_idx_is64;
__device__ int g_ds[NTOK];
// MoE routing scratch
__device__ int g_cnt[LE];
__device__ int g_off[LE+1];
__device__ int g_pos [NASSIGN];
__device__ int g_exp [NASSIGN];
__device__ int g_slot[NASSIGN];
__device__ int g_perm[NASSIGN];
__device__ int g_tileExp [MAXTILES];
__device__ int g_tileBase[MAXTILES];
__device__ int g_tileRows[MAXTILES];

// ---------------- indices dtype detection ----------------
__global__ void detect_idx_kernel(const void* idxbuf) {
    const unsigned long long* p = (const unsigned long long*)idxbuf;
    int is64 = 1;
    for (int i = 0; i < 256; i++) {
        if (p[i] > 7ULL) { is64 = 0; break; }
    }
    g_idx_is64 = is64;
}
__device__ __forceinline__ int load_expert_idx(const void* buf, long long f) {
    if (g_idx_is64) return ((int)((const long long*)buf)[f]) & 7;
    return (((const int*)buf)[f]) & 7;
}

// ---------------- doc start (doc sorted ascending) ----------------
__global__ void docstart_kernel(const int* __restrict__ doc) {
    int t = blockIdx.x*256 + threadIdx.x;
    if (t >= NTOK) return;
    int d = doc[t];
    int lo = 0, hi = t;
    while (lo < hi) { int mid = (lo+hi)>>1; if (doc[mid]==d) hi=mid; else lo=mid+1; }
    g_ds[t] = lo;
}

// ---------------- split helper ----------------
__device__ __forceinline__ void split1(float x, u16& h, u16& l) {
    __nv_bfloat16 hb = __float2bfloat16_rn(x);
    float hf = __bfloat162float(hb);
    __nv_bfloat16 lb = __float2bfloat16_rn(x - hf);
    h = *(u16*)&hb; l = *(u16*)&lb;
}

__device__ __forceinline__ void mma_bf16(float* c, const uint32_t* a, uint32_t b0, uint32_t b1) {
    asm volatile(
        "mma.sync.aligned.m16n8k16.row.col.f32.bf16.bf16.f32 "
        "{%0,%1,%2,%3}, {%4,%5,%6,%7}, {%8,%9}, {%0,%1,%2,%3};"
        : "+f"(c[0]), "+f"(c[1]), "+f"(c[2]), "+f"(c[3])
        : "r"(a[0]), "r"(a[1]), "r"(a[2]), "r"(a[3]), "r"(b0), "r"(b1));
}

// ---------------- weight conversion: [K,*] fp32 -> [N,K] bf16 hi/lo ----------------
// dest row = (source column)*cmul + cofs  (column interleaving for swiglu fusion)
__global__ void wconvT_kernel(const float* __restrict__ src, u16* __restrict__ hi, u16* __restrict__ lo,
                              int K, int srcStride, int colOff,
                              long long sSrc, long long sDst, int cmul, int cofs) {
    __shared__ float tile[32][33];
    src += (long long)blockIdx.z * sSrc;
    hi  += (long long)blockIdx.z * sDst;
    lo  += (long long)blockIdx.z * sDst;
    int n0 = blockIdx.x*32, k0 = blockIdx.y*32;
    int tx = threadIdx.x & 31, ty = threadIdx.x >> 5;
    #pragma unroll
    for (int j=0;j<32;j+=8)
        tile[ty+j][tx] = src[(long long)(k0+ty+j)*srcStride + colOff + n0+tx];
    __syncthreads();
    #pragma unroll
    for (int j=0;j<32;j+=8) {
        float v = tile[tx][ty+j];
        u16 h,l; split1(v,h,l);
        long long o = (long long)((n0+ty+j)*cmul + cofs)*K + k0+tx;
        hi[o]=h; lo[o]=l;
    }
}

__global__ void wconv_kernel(const float* __restrict__ src, u16* __restrict__ hi,
                             u16* __restrict__ lo) {
    long long i = (long long)blockIdx.x*256 + threadIdx.x;
    u16 h,l; split1(src[i],h,l);
    hi[i]=h; lo[i]=l;
}

// ---------------- double-buffered 3x-bf16 split GEMM ----------------
#define SMS 17
#define PLANE (2*128*SMS)
#define SMEM_BYTES (4*PLANE*4)

struct TileRegs { uint4 ah[2], al[2], bh[2], bl[2]; };

__device__ __forceinline__ void gemm_store_tile(uint32_t* S, int buf, int rA, int hA,
                                                const TileRegs& r) {
    uint32_t* AhP = S;
    uint32_t* AlP = S + PLANE;
    uint32_t* BhP = S + 2*PLANE;
    uint32_t* BlP = S + 3*PLANE;
    int base = (buf*128 + rA)*SMS + hA*8;
    AhP[base+0]=r.ah[0].x; AhP[base+1]=r.ah[0].y; AhP[base+2]=r.ah[0].z; AhP[base+3]=r.ah[0].w;
    AhP[base+4]=r.ah[1].x; AhP[base+5]=r.ah[1].y; AhP[base+6]=r.ah[1].z; AhP[base+7]=r.ah[1].w;
    AlP[base+0]=r.al[0].x; AlP[base+1]=r.al[0].y; AlP[base+2]=r.al[0].z; AlP[base+3]=r.al[0].w;
    AlP[base+4]=r.al[1].x; AlP[base+5]=r.al[1].y; AlP[base+6]=r.al[1].z; AlP[base+7]=r.al[1].w;
    BhP[base+0]=r.bh[0].x; BhP[base+1]=r.bh[0].y; BhP[base+2]=r.bh[0].z; BhP[base+3]=r.bh[0].w;
    BhP[base+4]=r.bh[1].x; BhP[base+5]=r.bh[1].y; BhP[base+6]=r.bh[1].z; BhP[base+7]=r.bh[1].w;
    BlP[base+0]=r.bl[0].x; BlP[base+1]=r.bl[0].y; BlP[base+2]=r.bl[0].z; BlP[base+3]=r.bl[0].w;
    BlP[base+4]=r.bl[1].x; BlP[base+5]=r.bl[1].y; BlP[base+6]=r.bl[1].z; BlP[base+7]=r.bl[1].w;
}

__device__ __forceinline__ void gemm_load_tile(TileRegs& r,
    const u16*& Agh, const u16*& Agl, const u16*& Bgh, const u16*& Bgl) {
    r.ah[0]=*(const uint4*)(Agh); r.ah[1]=*(const uint4*)(Agh+8);
    r.al[0]=*(const uint4*)(Agl); r.al[1]=*(const uint4*)(Agl+8);
    r.bh[0]=*(const uint4*)(Bgh); r.bh[1]=*(const uint4*)(Bgh+8);
    r.bl[0]=*(const uint4*)(Bgl); r.bl[1]=*(const uint4*)(Bgl+8);
    Agh+=32; Agl+=32; Bgh+=32; Bgl+=32;
}

__device__ __forceinline__ void gemm_compute(const uint32_t* S, int buf,
    int wm, int wn, int gid, int tig, float acc[2][8][4]) {
    const uint32_t* AhP = S;
    const uint32_t* AlP = S + PLANE;
    const uint32_t* BhP = S + 2*PLANE;
    const uint32_t* BlP = S + 3*PLANE;
    int rb = buf*128;
    #pragma unroll
    for (int kk = 0; kk < 16; kk += 8) {
        uint32_t ah[2][4], al[2][4];
        #pragma unroll
        for (int mt=0;mt<2;mt++) {
            int r0 = rb + wm*32 + mt*16 + gid;
            ah[mt][0]=AhP[(r0  )*SMS + kk+tig  ];
            ah[mt][1]=AhP[(r0+8)*SMS + kk+tig  ];
            ah[mt][2]=AhP[(r0  )*SMS + kk+tig+4];
            ah[mt][3]=AhP[(r0+8)*SMS + kk+tig+4];
            al[mt][0]=AlP[(r0  )*SMS + kk+tig  ];
            al[mt][1]=AlP[(r0+8)*SMS + kk+tig  ];
            al[mt][2]=AlP[(r0  )*SMS + kk+tig+4];
            al[mt][3]=AlP[(r0+8)*SMS + kk+tig+4];
        }
        #pragma unroll
        for (int nt=0;nt<8;nt++) {
            int col = rb + wn*64 + nt*8 + gid;
            uint32_t bh0=BhP[col*SMS + kk+tig  ];
            uint32_t bh1=BhP[col*SMS + kk+tig+4];
            uint32_t bl0=BlP[col*SMS + kk+tig  ];
            uint32_t bl1=BlP[col*SMS + kk+tig+4];
            #pragma unroll
            for (int mt=0;mt<2;mt++) {
                mma_bf16(acc[mt][nt], ah[mt], bh0, bh1);
                mma_bf16(acc[mt][nt], ah[mt], bl0, bl1);
                mma_bf16(acc[mt][nt], al[mt], bh0, bh1);
            }
        }
    }
}

__device__ __forceinline__ float silu_mul(float a, float b) {
    return (a / (1.f + __expf(-a))) * b;
}

// Oh!=null => swiglu epilogue: adjacent column pairs (x1,x2) -> silu(x1)*x2, split-bf16 out [M, N/2]
__global__ __launch_bounds__(256) void bf16gemm_kernel(
    const u16* __restrict__ Ah_g, const u16* __restrict__ Al_g,
    const u16* __restrict__ Bh_g, const u16* __restrict__ Bl_g,
    float* __restrict__ C, const float* __restrict__ R,
    u16* __restrict__ Oh, u16* __restrict__ Ol,
    int M, int N, int K)
{
    extern __shared__ uint32_t S[];
    const int bm = blockIdx.y, bn = blockIdx.x;
    const int t = threadIdx.x;
    const int lane = t & 31, wid = t >> 5;
    const int gid = lane >> 2, tig = lane & 3;
    const int wm = wid >> 1, wn = wid & 1;
    const int rA = t >> 1, hA = t & 1;

    const u16* Agh = Ah_g + (long long)(bm*128 + rA) * K + hA*16;
    const u16* Agl = Al_g + (long long)(bm*128 + rA) * K + hA*16;
    const u16* Bgh = Bh_g + (long long)(bn*128 + rA) * K + hA*16;
    const u16* Bgl = Bl_g + (long long)(bn*128 + rA) * K + hA*16;

    float acc[2][8][4];
    #pragma unroll
    for (int mt=0;mt<2;mt++)
        #pragma unroll
        for (int nt=0;nt<8;nt++)
            #pragma unroll
            for (int i=0;i<4;i++) acc[mt][nt][i]=0.f;

    TileRegs tr;
    gemm_load_tile(tr, Agh, Agl, Bgh, Bgl);
    gemm_store_tile(S, 0, rA, hA, tr);
    __syncthreads();

    int buf = 0;
    for (int k0 = 0; k0 < K; k0 += 32) {
        bool more = (k0 + 32 < K);
        if (more) gemm_load_tile(tr, Agh, Agl, Bgh, Bgl);
        gemm_compute(S, buf, wm, wn, gid, tig, acc);
        if (more) gemm_store_tile(S, buf^1, rA, hA, tr);
        buf ^= 1;
        __syncthreads();
    }

    if (Oh) {
        int Nout = N >> 1;
        #pragma unroll
        for (int mt=0;mt<2;mt++) {
            #pragma unroll
            for (int nt=0;nt<8;nt++) {
                long long row0 = (long long)bm*128 + wm*32 + mt*16 + gid;
                int col0 = bn*128 + wn*64 + nt*8 + tig*2;
                int oc = col0 >> 1;
                float r0 = silu_mul(acc[mt][nt][0], acc[mt][nt][1]);
                float r1 = silu_mul(acc[mt][nt][2], acc[mt][nt][3]);
                u16 h,l;
                split1(r0,h,l); Oh[row0*Nout+oc]=h;     Ol[row0*Nout+oc]=l;
                split1(r1,h,l); Oh[(row0+8)*Nout+oc]=h; Ol[(row0+8)*Nout+oc]=l;
            }
        }
    } else {
        #pragma unroll
        for (int mt=0;mt<2;mt++) {
            #pragma unroll
            for (int nt=0;nt<8;nt++) {
                long long row0 = (long long)bm*128 + wm*32 + mt*16 + gid;
                long long col0 = (long long)bn*128 + wn*64 + nt*8 + tig*2;
                long long i0 = row0*N + col0;
                long long i1 = (row0+8)*N + col0;
                float2 v0 = make_float2(acc[mt][nt][0], acc[mt][nt][1]);
                float2 v1 = make_float2(acc[mt][nt][2], acc[mt][nt][3]);
                if (R) {
                    float2 r0v = *(const float2*)(R + i0);
                    float2 r1v = *(const float2*)(R + i1);
                    v0.x += r0v.x; v0.y += r0v.y; v1.x += r1v.x; v1.y += r1v.y;
                }
                *(float2*)(C + i0) = v0;
                *(float2*)(C + i1) = v1;
            }
        }
    }
}

__global__ __launch_bounds__(256) void moe_gemm_kernel(
    const u16* __restrict__ Ah_g, const u16* __restrict__ Al_g,
    const u16* __restrict__ Wh, const u16* __restrict__ Wl,
    float* __restrict__ C, u16* __restrict__ Oh, u16* __restrict__ Ol,
    int N, int K, long long Wstride)
{
    extern __shared__ uint32_t S[];
    const int bt = blockIdx.y;
    const int e = g_tileExp[bt];
    if (e < 0) return;
    const int rowbase = g_tileBase[bt];
    const int mvalid  = g_tileRows[bt];
    const u16* Bh_g = Wh + (long long)e * Wstride;
    const u16* Bl_g = Wl + (long long)e * Wstride;

    const int bn = blockIdx.x;
    const int t = threadIdx.x;
    const int lane = t & 31, wid = t >> 5;
    const int gid = lane >> 2, tig = lane & 3;
    const int wm = wid >> 1, wn = wid & 1;
    const int rA = t >> 1, hA = t & 1;
    const int rAc = (rA < mvalid) ? rA : (mvalid - 1);

    const u16* Agh = Ah_g + (long long)(rowbase + rAc) * K + hA*16;
    const u16* Agl = Al_g + (long long)(rowbase + rAc) * K + hA*16;
    const u16* Bgh = Bh_g + (long long)(bn*128 + rA) * K + hA*16;
    const u16* Bgl = Bl_g + (long long)(bn*128 + rA) * K + hA*16;

    float acc[2][8][4];
    #pragma unroll
    for (int mt=0;mt<2;mt++)
        #pragma unroll
        for (int nt=0;nt<8;nt++)
            #pragma unroll
            for (int i=0;i<4;i++) acc[mt][nt][i]=0.f;

    TileRegs tr;
    gemm_load_tile(tr, Agh, Agl, Bgh, Bgl);
    gemm_store_tile(S, 0, rA, hA, tr);
    __syncthreads();

    int buf = 0;
    for (int k0 = 0; k0 < K; k0 += 32) {
        bool more = (k0 + 32 < K);
        if (more) gemm_load_tile(tr, Agh, Agl, Bgh, Bgl);
        gemm_compute(S, buf, wm, wn, gid, tig, acc);
        if (more) gemm_store_tile(S, buf^1, rA, hA, tr);
        buf ^= 1;
        __syncthreads();
    }

    if (Oh) {
        int Nout = N >> 1;
        #pragma unroll
        for (int mt=0;mt<2;mt++) {
            int rl0 = wm*32 + mt*16 + gid;
            int rl1 = rl0 + 8;
            #pragma unroll
            for (int nt=0;nt<8;nt++) {
                int col0 = bn*128 + wn*64 + nt*8 + tig*2;
                int oc = col0 >> 1;
                if (rl0 < mvalid) {
                    float r0 = silu_mul(acc[mt][nt][0], acc[mt][nt][1]);
                    u16 h,l; split1(r0,h,l);
                    long long o = (long long)(rowbase + rl0)*Nout + oc;
                    Oh[o]=h; Ol[o]=l;
                }
                if (rl1 < mvalid) {
                    float r1 = silu_mul(acc[mt][nt][2], acc[mt][nt][3]);
                    u16 h,l; split1(r1,h,l);
                    long long o = (long long)(rowbase + rl1)*Nout + oc;
                    Oh[o]=h; Ol[o]=l;
                }
            }
        }
    } else {
        #pragma unroll
        for (int mt=0;mt<2;mt++) {
            int rl0 = wm*32 + mt*16 + gid;
            int rl1 = rl0 + 8;
            #pragma unroll
            for (int nt=0;nt<8;nt++) {
                long long col0 = (long long)bn*128 + wn*64 + nt*8 + tig*2;
                if (rl0 < mvalid) {
                    long long i0 = (long long)(rowbase + rl0)*N + col0;
                    *(float2*)(C + i0) = make_float2(acc[mt][nt][0], acc[mt][nt][1]);
                }
                if (rl1 < mvalid) {
                    long long i1 = (long long)(rowbase + rl1)*N + col0;
                    *(float2*)(C + i1) = make_float2(acc[mt][nt][2], acc[mt][nt][3]);
                }
            }
        }
    }
}

// ---------------- MoE routing-permutation kernels ----------------
__global__ void zero_cnt_kernel() {
    if (threadIdx.x < LE) g_cnt[threadIdx.x] = 0;
}
__global__ void assign1_kernel(const void* __restrict__ idx, long long idxOff) {
    int n = blockIdx.x*blockDim.x + threadIdx.x;
    if (n >= NTOK) return;
    #pragma unroll
    for (int k=0;k<TOPK;k++) {
        int f = n*TOPK + k;
        int e = load_expert_idx(idx, idxOff + f);
        g_exp[f] = e;
        g_pos[f] = atomicAdd(&g_cnt[e], 1);
    }
}
__global__ void scan_tiles_kernel() {
    int off = 0;
    for (int e=0;e<LE;e++) { g_off[e]=off; off += g_cnt[e]; }
    g_off[LE]=off;
    int t = 0;
    for (int e=0;e<LE;e++) {
        int c = g_cnt[e];
        for (int j=0;j<c;j+=128) {
            g_tileExp[t]=e; g_tileBase[t]=g_off[e]+j;
            g_tileRows[t]=min(128, c-j);
            t++;
        }
    }
    for (;t<MAXTILES;t++) g_tileExp[t]=-1;
}
__global__ void assign2_kernel() {
    int f = blockIdx.x*blockDim.x + threadIdx.x;
    if (f >= NASSIGN) return;
    int slot = g_off[g_exp[f]] + g_pos[f];
    g_slot[f] = slot;
    g_perm[slot] = f / TOPK;
}
__global__ void gather_kernel() {
    int slot = blockIdx.x;
    int n = g_perm[slot];
    int t = threadIdx.x;
    if (t < 128) {
        const uint4* src = (const uint4*)(g_sxnh + (long long)n*DIM);
        uint4* dst = (uint4*)(g_sxph + (long long)slot*DIM);
        dst[t] = src[t];
    } else {
        const uint4* src = (const uint4*)(g_sxnl + (long long)n*DIM);
        uint4* dst = (uint4*)(g_sxpl + (long long)slot*DIM);
        dst[t-128] = src[t-128];
    }
}
__global__ void combine2_kernel(float* __restrict__ xout, const float* __restrict__ yp,
                                const float* __restrict__ sc) {
    long long i = (long long)blockIdx.x*256 + threadIdx.x;
    int n = (int)(i >> 10);
    #pragma unroll
    for (int k=0;k<TOPK;k++){
        int f = n*TOPK + k;
        xout[i] += sc[f] * yp[(long long)g_slot[f]*DIM + (int)(i & 1023)];
    }
}

// ---------------- RMSNorm (fused split output) ----------------
__global__ void rmsnorm_kernel(const float* __restrict__ x, const float* __restrict__ g,
                               float* __restrict__ o) {
    int n = blockIdx.x, tid = threadIdx.x;
    const float* xr = x + (long long)n*DIM;
    float s = 0.f;
    for (int d=tid; d<DIM; d+=256){ float v=xr[d]; s += v*v; }
    __shared__ float red[256];
    red[tid]=s; __syncthreads();
    for (int st=128; st>0; st>>=1){ if(tid<st) red[tid]+=red[tid+st]; __syncthreads(); }
    float scale = rsqrtf(red[0]/(float)DIM + 1e-6f);
    float* orow = o + (long long)n*DIM;
    u16* hrow = g_sxnh + (long long)n*DIM;
    u16* lrow = g_sxnl + (long long)n*DIM;
    for (int d=tid; d<DIM; d+=256) {
        float v = xr[d]*scale*g[d];
        orow[d] = v;
        u16 h,l; split1(v,h,l);
        hrow[d]=h; lrow[d]=l;
    }
}

// ---------------- RoPE ----------------
__global__ void rope_kernel(float* __restrict__ qkv) {
    int s = blockIdx.x;
    int t = threadIdx.x;
    int isK = t >> 9;
    int p = t & 511;
    int h = p >> 5;
    int j = p & 31;
    float* base = qkv + (long long)s*3*DIM + isK*DIM + h*HEADD;
    float inv = powf(10000.0f, -(float)j/32.0f);
    float ang = (float)s * inv;
    float sn, c; sincosf(ang, &sn, &c);
    float x1 = base[j], x2 = base[j+32];
    base[j]    =  x1*c + x2*sn;
    base[j+32] = -x1*sn + x2*c;
}

// ---------------- flash-style attention (doc-skip + fused split output) ----------------
__global__ __launch_bounds__(64) void attn_kernel(const float* __restrict__ qkv,
                                                  const int* __restrict__ doc) {
    int h  = blockIdx.y;
    int qt = blockIdx.x;
    int tid = threadIdx.x;
    int qg = qt*64 + tid;
    __shared__ float Ks[64][68];
    __shared__ float Vs[64][68];
    __shared__ int docs[64];
    float q[64], acc[64];
    const float* qp = qkv + (long long)qg*3*DIM + h*HEADD;
    #pragma unroll
    for (int d=0; d<64; d+=4) {
        float4 v = *(const float4*)(qp + d);
        q[d]=v.x; q[d+1]=v.y; q[d+2]=v.z; q[d+3]=v.w;
    }
    #pragma unroll
    for (int d=0; d<64; d++) acc[d]=0.f;
    int dq = doc[qg];
    float m = -1e30f, l = 0.f;

    int ktb = g_ds[qt*64] >> 6;
    for (int kt=ktb; kt<=qt; kt++) {
        const float* kp = qkv + (long long)(kt*64+tid)*3*DIM + DIM + h*HEADD;
        const float* vp = kp + DIM;
        #pragma unroll
        for (int d=0; d<64; d+=4) {
            *(float4*)&Ks[tid][d] = *(const float4*)(kp+d);
            *(float4*)&Vs[tid][d] = *(const float4*)(vp+d);
        }
        docs[tid] = doc[kt*64+tid];
        __syncthreads();
        int jmax = min(64, qg - kt*64 + 1);
        for (int j=0; j<jmax; j++) {
            if (docs[j] == dq) {
                float s0=0,s1=0,s2=0,s3=0;
                #pragma unroll
                for (int d=0; d<64; d+=4) {
                    float4 kv = *(const float4*)&Ks[j][d];
                    s0 += q[d]  *kv.x; s1 += q[d+1]*kv.y;
                    s2 += q[d+2]*kv.z; s3 += q[d+3]*kv.w;
                }
                float s = ((s0+s1)+(s2+s3))*0.125f;
                float mn  = fmaxf(m, s);
                float corr = __expf(m - mn);
                float pexp = __expf(s - mn);
                l = l*corr + pexp;
                #pragma unroll
                for (int d=0; d<64; d+=4) {
                    float4 vv = *(const float4*)&Vs[j][d];
                    acc[d]   = acc[d]  *corr + pexp*vv.x;
                    acc[d+1] = acc[d+1]*corr + pexp*vv.y;
                    acc[d+2] = acc[d+2]*corr + pexp*vv.z;
                    acc[d+3] = acc[d+3]*corr + pexp*vv.w;
                }
                m = mn;
            }
        }
        __syncthreads();
    }
    float inv = 1.0f / l;
    u16 oh[64], ol[64];
    #pragma unroll
    for (int d=0; d<64; d++) split1(acc[d]*inv, oh[d], ol[d]);
    u16* ph = g_satth + (long long)qg*DIM + h*HEADD;
    u16* pl = g_sattl + (long long)qg*DIM + h*HEADD;
    #pragma unroll
    for (int d=0; d<64; d+=8) {
        *(uint4*)(ph + d) = *(uint4*)(oh + d);
        *(uint4*)(pl + d) = *(uint4*)(ol + d);
    }
}

// ---------------- router ----------------
__global__ void router_tv_kernel(const float* __restrict__ xf, const float* __restrict__ tk,
                                 float* __restrict__ tv) {
    int n = blockIdx.x, tid = threadIdx.x;
    float p[LE];
    #pragma unroll
    for (int e=0;e<LE;e++) p[e]=0.f;
    const float* xr = xf + (long long)n*DIM;
    for (int d=tid; d<DIM; d+=256) {
        float x = xr[d];
        const float* tkr = tk + (long long)d*LE;
        #pragma unroll
        for (int e=0;e<LE;e++) p[e] += x*tkr[e];
    }
    __shared__ float red[LE][256];
    #pragma unroll
    for (int e=0;e<LE;e++) red[e][tid]=p[e];
    __syncthreads();
    for (int st=128; st>0; st>>=1) {
        if (tid < st) {
            #pragma unroll
            for (int e=0;e<LE;e++) red[e][tid]+=red[e][tid+st];
        }
        __syncthreads();
    }
    if (tid < LE) tv[(long long)n*LE + tid] = red[tid][0];
}

__global__ void router_score_kernel(const float* __restrict__ tv, const void* __restrict__ idx,
                                    long long idxOff,
                                    const float* __restrict__ vals, const float* __restrict__ rb,
                                    float* __restrict__ sc) {
    int n = blockIdx.x*blockDim.x + threadIdx.x;
    if (n >= NTOK) return;
    float s[TOPK];
    #pragma unroll
    for (int k=0;k<TOPK;k++){
        int e = load_expert_idx(idx, idxOff + (long long)n*TOPK + k);
        float v = vals[(long long)n*TOPK+k] + tv[(long long)n*LE+e] + rb[e];
        s[k] = 1.f/(1.f+__expf(-v));
    }
    float inv = 1.f/(s[0]+s[1]);
    sc[(long long)n*TOPK+0] = s[0]*inv;
    sc[(long long)n*TOPK+1] = s[1]*inv;
}

// ---------------- host ----------------
extern "C" void kernel_launch(void* const* d_in, const int* in_sizes, int n_in,
                              void* d_out, int out_size) {
    const float* x       = (const float*)d_in[0];
    const int*   doc     = (const int*)d_in[1];
    const void*  indices = d_in[2];
    const float* values  = (const float*)d_in[3];
    const float* daw = (const float*)d_in[4];
    const float* dao = (const float*)d_in[5];
    const float* dup = (const float*)d_in[6];
    const float* ddn = (const float*)d_in[7];
    const float* dag = (const float*)d_in[8];
    const float* dfg = (const float*)d_in[9];
    const float* maw = (const float*)d_in[10];
    const float* mao = (const float*)d_in[11];
    const float* mag = (const float*)d_in[12];
    const float* mfg = (const float*)d_in[13];
    const float* mex = (const float*)d_in[14];
    const float* mtk = (const float*)d_in[15];
    const float* mrb = (const float*)d_in[16];
    const float* msup= (const float*)d_in[17];
    const float* msdn= (const float*)d_in[18];
    float* out = (float*)d_out;

    void* p;
    cudaGetSymbolAddress(&p, g_wh);    u16* WH = (u16*)p;
    cudaGetSymbolAddress(&p, g_wl);    u16* WL = (u16*)p;
    cudaGetSymbolAddress(&p, g_sxnh);  u16* SXNH=(u16*)p;
    cudaGetSymbolAddress(&p, g_sxnl);  u16* SXNL=(u16*)p;
    cudaGetSymbolAddress(&p, g_satth); u16* SATTH=(u16*)p;
    cudaGetSymbolAddress(&p, g_sattl); u16* SATTL=(u16*)p;
    cudaGetSymbolAddress(&p, g_shh);   u16* SHH=(u16*)p;
    cudaGetSymbolAddress(&p, g_shl);   u16* SHL=(u16*)p;
    cudaGetSymbolAddress(&p, g_sxph);  u16* SXPH=(u16*)p;
    cudaGetSymbolAddress(&p, g_sxpl);  u16* SXPL=(u16*)p;
    cudaGetSymbolAddress(&p, g_shsh);  u16* SHSH=(u16*)p;
    cudaGetSymbolAddress(&p, g_shsl);  u16* SHSL=(u16*)p;
    cudaGetSymbolAddress(&p, g_xn);   float* XN  = (float*)p;
    cudaGetSymbolAddress(&p, g_qkv);  float* QKV = (float*)p;
    cudaGetSymbolAddress(&p, g_xi);   float* XI  = (float*)p;
    cudaGetSymbolAddress(&p, g_yp);   float* YP  = (float*)p;
    cudaGetSymbolAddress(&p, g_tv);   float* TV  = (float*)p;
    cudaGetSymbolAddress(&p, g_sc);   float* SC  = (float*)p;
    cudaGetSymbolAddress(&p, g_xa);   float* XA  = (float*)p;
    cudaGetSymbolAddress(&p, g_xb);   float* XB  = (float*)p;

    static int attr_done = 0;
    if (!attr_done) {
        cudaFuncSetAttribute(bf16gemm_kernel, cudaFuncAttributeMaxDynamicSharedMemorySize, SMEM_BYTES);
        cudaFuncSetAttribute(moe_gemm_kernel, cudaFuncAttributeMaxDynamicSharedMemorySize, SMEM_BYTES);
        attr_done = 1;
    }

    detect_idx_kernel<<<1,1>>>(indices);
    docstart_kernel<<<(NTOK+255)/256,256>>>(doc);

    // ---- weight conversion passes ----
    auto convT = [&](const float* src, long long off, int K, int Ncols, int stride, int colOff,
                     int batch, long long sSrc, long long sDst, int cmul, int cofs){
        wconvT_kernel<<<dim3(Ncols/32, K/32, batch),256>>>(src, WH+off, WL+off, K, stride, colOff,
                                                           sSrc, sDst, cmul, cofs);
    };
    convT(daw, OFF_DAW, 1024, 3072, 3072, 0, 2, 3072LL*1024, 3072LL*1024, 1, 0);
    convT(dao, OFF_DAO, 1024, 1024, 1024, 0, 2, 1024LL*1024, 1024LL*1024, 1, 0);
    // up: interleave x1/x2 column pairs for fused swiglu
    convT(dup, OFF_DUP, 1024, 4096, 8192, 0,    2, 8192LL*1024, 8192LL*1024, 2, 0);
    convT(dup, OFF_DUP, 1024, 4096, 8192, 4096, 2, 8192LL*1024, 8192LL*1024, 2, 1);
    convT(ddn, OFF_DDN, 4096, 1024, 1024, 0, 2, 1024LL*4096, 1024LL*4096, 1, 0);
    convT(maw, OFF_MAW, 1024, 3072, 3072, 0, 2, 3072LL*1024, 3072LL*1024, 1, 0);
    convT(mao, OFF_MAO, 1024, 1024, 1024, 0, 2, 1024LL*1024, 1024LL*1024, 1, 0);
    for (int i=0;i<2;i++) {
        const float* W1 = mex + ((long long)i*3+0)*LE*DIM*DIME;
        const float* W2 = mex + ((long long)i*3+1)*LE*DIM*DIME;
        const float* W3 = mex + ((long long)i*3+2)*LE*DIM*DIME;
        long long w12o = OFF_W12 + (long long)i*LE*1024*1024;
        convT(W1, w12o, 1024, 512, 512, 0, 8, (long long)DIM*DIME, 1024LL*1024, 2, 0);
        convT(W2, w12o, 1024, 512, 512, 0, 8, (long long)DIM*DIME, 1024LL*1024, 2, 1);
        wconv_kernel<<<(LE*DIM*DIME)/256,256>>>(W3, WH + OFF_W3 + (long long)i*LE*DIM*DIME,
                                                WL + OFF_W3 + (long long)i*LE*DIM*DIME);
    }
    convT(msup, OFF_MSUP, 1024, 1024, 2048, 0,    2, 2048LL*1024, 2048LL*1024, 2, 0);
    convT(msup, OFF_MSUP, 1024, 1024, 2048, 1024, 2, 2048LL*1024, 2048LL*1024, 2, 1);
    convT(msdn, OFF_MSDN, 1024, 1024, 1024, 0, 2, 1024LL*1024, 1024LL*1024, 1, 0);

    auto gemm = [&](const u16* Ah, const u16* Al, long long woff, float* C,
                    int M, int N, int K, const float* R){
        bf16gemm_kernel<<<dim3(N/128, M/128), 256, SMEM_BYTES>>>(
            Ah, Al, WH+woff, WL+woff, C, R, nullptr, nullptr, M, N, K);
    };
    auto gemm_swiglu = [&](const u16* Ah, const u16* Al, long long woff,
                           u16* Oh, u16* Ol, int M, int N, int K){
        bf16gemm_kernel<<<dim3(N/128, M/128), 256, SMEM_BYTES>>>(
            Ah, Al, WH+woff, WL+woff, nullptr, nullptr, Oh, Ol, M, N, K);
    };

    auto attn_block = [&](const float* xin, long long awoff, long long aooff, const float* ag){
        rmsnorm_kernel<<<NTOK,256>>>(xin, ag, XN);
        gemm(SXNH, SXNL, awoff, QKV, NTOK, 3*DIM, DIM, nullptr);
        rope_kernel<<<NTOK,1024>>>(QKV);
        attn_kernel<<<dim3(NTOK/64, HEADS),64>>>(QKV, doc);
        gemm(SATTH, SATTL, aooff, XI, NTOK, DIM, DIM, xin);
    };

    auto dense = [&](const float* xin, float* xout, int l){
        attn_block(xin, OFF_DAW + (long long)l*3072*1024, OFF_DAO + (long long)l*1024*1024,
                   dag + (long long)l*DIM);
        rmsnorm_kernel<<<NTOK,256>>>(XI, dfg + (long long)l*DIM, XN);
        gemm_swiglu(SXNH, SXNL, OFF_DUP + (long long)l*8192*1024, SHH, SHL, NTOK, 2*FFNH, DIM);
        gemm(SHH, SHL, OFF_DDN + (long long)l*1024*4096, xout, NTOK, DIM, FFNH, XI);
    };

    auto moe = [&](const float* xin, float* xout, int i){
        attn_block(xin, OFF_MAW + (long long)i*3072*1024, OFF_MAO + (long long)i*1024*1024,
                   mag + (long long)i*DIM);
        rmsnorm_kernel<<<NTOK,256>>>(XI, mfg + (long long)i*DIM, XN);
        long long idxOff = (long long)i*NTOK*TOPK;

        router_tv_kernel<<<NTOK,256>>>(XN, mtk + (long long)i*DIM*LE, TV);
        router_score_kernel<<<(NTOK+255)/256,256>>>(TV, indices, idxOff,
                                                    values + idxOff,
                                                    mrb + (long long)i*LE, SC);
        zero_cnt_kernel<<<1,32>>>();
        assign1_kernel<<<(NTOK+255)/256,256>>>(indices, idxOff);
        scan_tiles_kernel<<<1,1>>>();
        assign2_kernel<<<(NASSIGN+255)/256,256>>>();
        gather_kernel<<<NASSIGN,256>>>();

        long long w12o = OFF_W12 + (long long)i*LE*1024*1024;
        long long w3o  = OFF_W3  + (long long)i*LE*DIM*DIME;
        // fused W1|W2 grouped GEMM with swiglu epilogue -> SHSH/SHSL
        moe_gemm_kernel<<<dim3(2*DIME/128, MAXTILES), 256, SMEM_BYTES>>>(
            SXPH, SXPL, WH+w12o, WL+w12o, nullptr, SHSH, SHSL, 2*DIME, DIM, 1024LL*1024);
        // down projection
        moe_gemm_kernel<<<dim3(DIM/128, MAXTILES), 256, SMEM_BYTES>>>(
            SHSH, SHSL, WH+w3o, WL+w3o, YP, nullptr, nullptr, DIM, DIME, (long long)DIM*DIME);

        // shared expert (fused swiglu up, then down)
        gemm_swiglu(SXNH, SXNL, OFF_MSUP + (long long)i*2048*1024, SHH, SHL, NTOK, 2*DIMS, DIM);
        gemm(SHH, SHL, OFF_MSDN + (long long)i*1024*1024, xout, NTOK, DIM, DIMS, XI);

        combine2_kernel<<<(NTOK*DIM)/256,256>>>(xout, YP, SC);
    };

    dense(x,  XA, 0);
    moe  (XA, XB, 0);
    moe  (XB, XA, 1);
    dense(XA, out, 1);
}

// round 16
// speedup vs baseline: 1.0742x; 1.0742x over previous
#include <cuda_runtime.h>
#include <cuda_bf16.h>
#include <math.h>
#include <stdint.h>

#define NTOK 2048
#define DIM  1024
#define HEADS 16
#define HEADD 64
#define FFNH 4096
#define LE   8
#define TOPK 2
#define DIME 512
#define DIMS 1024
#define NASSIGN (NTOK*TOPK)
#define MAXTILES 40

typedef unsigned short u16;

// ---------------- weight split arena offsets (elements) ----------------
#define OFF_DAW  0LL
#define OFF_DAO  6291456LL
#define OFF_DUP  8388608LL
#define OFF_DDN  25165824LL
#define OFF_MAW  33554432LL
#define OFF_MAO  39845888LL
#define OFF_W1   41943040LL
#define OFF_W2   50331648LL
#define OFF_W3   58720256LL
#define OFF_MSUP 67108864LL
#define OFF_MSDN 71303168LL
#define WTOTAL   73400320LL

// ---------------- scratch (device globals; no allocation) ----------------
__device__ __align__(16) u16 g_wh[WTOTAL];
__device__ __align__(16) u16 g_wl[WTOTAL];
__device__ __align__(16) u16 g_sxnh[NTOK*DIM],   g_sxnl[NTOK*DIM];
__device__ __align__(16) u16 g_satth[NTOK*DIM],  g_sattl[NTOK*DIM];
__device__ __align__(16) u16 g_shh[NTOK*FFNH],   g_shl[NTOK*FFNH];
__device__ __align__(16) u16 g_sxph[NASSIGN*DIM],g_sxpl[NASSIGN*DIM];
__device__ __align__(16) u16 g_shsh[NASSIGN*DIME],g_shsl[NASSIGN*DIME];

__device__ __align__(16) float g_xn [NTOK*DIM];
__device__ __align__(16) float g_qkv[NTOK*3*DIM];
__device__ __align__(16) float g_xi [NTOK*DIM];
__device__ __align__(16) float g_u  [NTOK*2*FFNH];
__device__ __align__(16) float g_h1 [NASSIGN*DIME];
__device__ __align__(16) float g_h2 [NASSIGN*DIME];
__device__ __align__(16) float g_yp [NASSIGN*DIM];
__device__ __align__(16) float g_tv [NTOK*LE];
__device__ __align__(16) float g_sc [NTOK*TOPK];
__device__ __align__(16) float g_xa [NTOK*DIM];
__device__ __align__(16) float g_xb [NTOK*DIM];
__device__ int g_idx_is64;
__device__ int g_ds[NTOK];
// MoE routing scratch
__device__ int g_cnt[LE];
__device__ int g_off[LE+1];
__device__ int g_pos [NASSIGN];
__device__ int g_exp [NASSIGN];
__device__ int g_slot[NASSIGN];
__device__ int g_perm[NASSIGN];
__device__ int g_tileExp [MAXTILES];
__device__ int g_tileBase[MAXTILES];
__device__ int g_tileRows[MAXTILES];

// ---------------- indices dtype detection ----------------
__global__ void detect_idx_kernel(const void* idxbuf) {
    const unsigned long long* p = (const unsigned long long*)idxbuf;
    int is64 = 1;
    for (int i = 0; i < 256; i++) {
        if (p[i] > 7ULL) { is64 = 0; break; }
    }
    g_idx_is64 = is64;
}
__device__ __forceinline__ int load_expert_idx(const void* buf, long long f) {
    if (g_idx_is64) return ((int)((const long long*)buf)[f]) & 7;
    return (((const int*)buf)[f]) & 7;
}

// ---------------- doc start (doc sorted ascending) ----------------
__global__ void docstart_kernel(const int* __restrict__ doc) {
    int t = blockIdx.x*256 + threadIdx.x;
    if (t >= NTOK) return;
    int d = doc[t];
    int lo = 0, hi = t;
    while (lo < hi) { int mid = (lo+hi)>>1; if (doc[mid]==d) hi=mid; else lo=mid+1; }
    g_ds[t] = lo;
}

// ---------------- split helper ----------------
__device__ __forceinline__ void split1(float x, u16& h, u16& l) {
    __nv_bfloat16 hb = __float2bfloat16_rn(x);
    float hf = __bfloat162float(hb);
    __nv_bfloat16 lb = __float2bfloat16_rn(x - hf);
    h = *(u16*)&hb; l = *(u16*)&lb;
}

__device__ __forceinline__ void mma_bf16(float* c, const uint32_t* a, uint32_t b0, uint32_t b1) {
    asm volatile(
        "mma.sync.aligned.m16n8k16.row.col.f32.bf16.bf16.f32 "
        "{%0,%1,%2,%3}, {%4,%5,%6,%7}, {%8,%9}, {%0,%1,%2,%3};"
        : "+f"(c[0]), "+f"(c[1]), "+f"(c[2]), "+f"(c[3])
        : "r"(a[0]), "r"(a[1]), "r"(a[2]), "r"(a[3]), "r"(b0), "r"(b1));
}

// ---------------- weight conversion: [K,N] fp32 -> [N,K] bf16 hi/lo ----------------
__global__ void wconvT_kernel(const float* __restrict__ src, u16* __restrict__ hi, u16* __restrict__ lo,
                              int K, int N, long long sSrc, long long sDst) {
    __shared__ float tile[32][33];
    src += (long long)blockIdx.z * sSrc;
    hi  += (long long)blockIdx.z * sDst;
    lo  += (long long)blockIdx.z * sDst;
    int n0 = blockIdx.x*32, k0 = blockIdx.y*32;
    int tx = threadIdx.x & 31, ty = threadIdx.x >> 5;
    #pragma unroll
    for (int j=0;j<32;j+=8)
        tile[ty+j][tx] = src[(long long)(k0+ty+j)*N + n0+tx];
    __syncthreads();
    #pragma unroll
    for (int j=0;j<32;j+=8) {
        float v = tile[tx][ty+j];
        u16 h,l; split1(v,h,l);
        long long o = (long long)(n0+ty+j)*K + k0+tx;
        hi[o]=h; lo[o]=l;
    }
}

__global__ void wconv_kernel(const float* __restrict__ src, u16* __restrict__ hi,
                             u16* __restrict__ lo) {
    long long i = (long long)blockIdx.x*256 + threadIdx.x;
    u16 h,l; split1(src[i],h,l);
    hi[i]=h; lo[i]=l;
}

// ---------------- double-buffered 3x-bf16 split GEMM ----------------
#define SMS 17
#define PLANE (2*128*SMS)
#define SMEM_BYTES (4*PLANE*4)

struct TileRegs { uint4 ah[2], al[2], bh[2], bl[2]; };

__device__ __forceinline__ void gemm_store_tile(uint32_t* S, int buf, int rA, int hA,
                                                const TileRegs& r) {
    uint32_t* AhP = S;
    uint32_t* AlP = S + PLANE;
    uint32_t* BhP = S + 2*PLANE;
    uint32_t* BlP = S + 3*PLANE;
    int base = (buf*128 + rA)*SMS + hA*8;
    AhP[base+0]=r.ah[0].x; AhP[base+1]=r.ah[0].y; AhP[base+2]=r.ah[0].z; AhP[base+3]=r.ah[0].w;
    AhP[base+4]=r.ah[1].x; AhP[base+5]=r.ah[1].y; AhP[base+6]=r.ah[1].z; AhP[base+7]=r.ah[1].w;
    AlP[base+0]=r.al[0].x; AlP[base+1]=r.al[0].y; AlP[base+2]=r.al[0].z; AlP[base+3]=r.al[0].w;
    AlP[base+4]=r.al[1].x; AlP[base+5]=r.al[1].y; AlP[base+6]=r.al[1].z; AlP[base+7]=r.al[1].w;
    BhP[base+0]=r.bh[0].x; BhP[base+1]=r.bh[0].y; BhP[base+2]=r.bh[0].z; BhP[base+3]=r.bh[0].w;
    BhP[base+4]=r.bh[1].x; BhP[base+5]=r.bh[1].y; BhP[base+6]=r.bh[1].z; BhP[base+7]=r.bh[1].w;
    BlP[base+0]=r.bl[0].x; BlP[base+1]=r.bl[0].y; BlP[base+2]=r.bl[0].z; BlP[base+3]=r.bl[0].w;
    BlP[base+4]=r.bl[1].x; BlP[base+5]=r.bl[1].y; BlP[base+6]=r.bl[1].z; BlP[base+7]=r.bl[1].w;
}

__device__ __forceinline__ void gemm_load_tile(TileRegs& r,
    const u16*& Agh, const u16*& Agl, const u16*& Bgh, const u16*& Bgl) {
    r.ah[0]=*(const uint4*)(Agh); r.ah[1]=*(const uint4*)(Agh+8);
    r.al[0]=*(const uint4*)(Agl); r.al[1]=*(const uint4*)(Agl+8);
    r.bh[0]=*(const uint4*)(Bgh); r.bh[1]=*(const uint4*)(Bgh+8);
    r.bl[0]=*(const uint4*)(Bgl); r.bl[1]=*(const uint4*)(Bgl+8);
    Agh+=32; Agl+=32; Bgh+=32; Bgl+=32;
}

__device__ __forceinline__ void gemm_compute(const uint32_t* S, int buf,
    int wm, int wn, int gid, int tig, float acc[2][8][4]) {
    const uint32_t* AhP = S;
    const uint32_t* AlP = S + PLANE;
    const uint32_t* BhP = S + 2*PLANE;
    const uint32_t* BlP = S + 3*PLANE;
    int rb = buf*128;
    #pragma unroll
    for (int kk = 0; kk < 16; kk += 8) {
        uint32_t ah[2][4], al[2][4];
        #pragma unroll
        for (int mt=0;mt<2;mt++) {
            int r0 = rb + wm*32 + mt*16 + gid;
            ah[mt][0]=AhP[(r0  )*SMS + kk+tig  ];
            ah[mt][1]=AhP[(r0+8)*SMS + kk+tig  ];
            ah[mt][2]=AhP[(r0  )*SMS + kk+tig+4];
            ah[mt][3]=AhP[(r0+8)*SMS + kk+tig+4];
            al[mt][0]=AlP[(r0  )*SMS + kk+tig  ];
            al[mt][1]=AlP[(r0+8)*SMS + kk+tig  ];
            al[mt][2]=AlP[(r0  )*SMS + kk+tig+4];
            al[mt][3]=AlP[(r0+8)*SMS + kk+tig+4];
        }
        #pragma unroll
        for (int nt=0;nt<8;nt++) {
            int col = rb + wn*64 + nt*8 + gid;
            uint32_t bh0=BhP[col*SMS + kk+tig  ];
            uint32_t bh1=BhP[col*SMS + kk+tig+4];
            uint32_t bl0=BlP[col*SMS + kk+tig  ];
            uint32_t bl1=BlP[col*SMS + kk+tig+4];
            #pragma unroll
            for (int mt=0;mt<2;mt++) {
                mma_bf16(acc[mt][nt], ah[mt], bh0, bh1);
                mma_bf16(acc[mt][nt], ah[mt], bl0, bl1);
                mma_bf16(acc[mt][nt], al[mt], bh0, bh1);
            }
        }
    }
}

__global__ __launch_bounds__(256) void bf16gemm_kernel(
    const u16* __restrict__ Ah_g, const u16* __restrict__ Al_g,
    const u16* __restrict__ Bh_g, const u16* __restrict__ Bl_g,
    float* __restrict__ C, const float* __restrict__ R,
    int M, int N, int K)
{
    extern __shared__ uint32_t S[];
    const int bm = blockIdx.y, bn = blockIdx.x;
    const int t = threadIdx.x;
    const int lane = t & 31, wid = t >> 5;
    const int gid = lane >> 2, tig = lane & 3;
    const int wm = wid >> 1, wn = wid & 1;
    const int rA = t >> 1, hA = t & 1;

    const u16* Agh = Ah_g + (long long)(bm*128 + rA) * K + hA*16;
    const u16* Agl = Al_g + (long long)(bm*128 + rA) * K + hA*16;
    const u16* Bgh = Bh_g + (long long)(bn*128 + rA) * K + hA*16;
    const u16* Bgl = Bl_g + (long long)(bn*128 + rA) * K + hA*16;

    float acc[2][8][4];
    #pragma unroll
    for (int mt=0;mt<2;mt++)
        #pragma unroll
        for (int nt=0;nt<8;nt++)
            #pragma unroll
            for (int i=0;i<4;i++) acc[mt][nt][i]=0.f;

    TileRegs tr;
    gemm_load_tile(tr, Agh, Agl, Bgh, Bgl);
    gemm_store_tile(S, 0, rA, hA, tr);
    __syncthreads();

    int buf = 0;
    for (int k0 = 0; k0 < K; k0 += 32) {
        bool more = (k0 + 32 < K);
        if (more) gemm_load_tile(tr, Agh, Agl, Bgh, Bgl);
        gemm_compute(S, buf, wm, wn, gid, tig, acc);
        if (more) gemm_store_tile(S, buf^1, rA, hA, tr);
        buf ^= 1;
        __syncthreads();
    }

    #pragma unroll
    for (int mt=0;mt<2;mt++) {
        #pragma unroll
        for (int nt=0;nt<8;nt++) {
            long long row0 = (long long)bm*128 + wm*32 + mt*16 + gid;
            long long col0 = (long long)bn*128 + wn*64 + nt*8 + tig*2;
            long long i0 = row0*N + col0;
            long long i1 = (row0+8)*N + col0;
            float2 v0 = make_float2(acc[mt][nt][0], acc[mt][nt][1]);
            float2 v1 = make_float2(acc[mt][nt][2], acc[mt][nt][3]);
            if (R) {
                float2 r0v = *(const float2*)(R + i0);
                float2 r1v = *(const float2*)(R + i1);
                v0.x += r0v.x; v0.y += r0v.y; v1.x += r1v.x; v1.y += r1v.y;
            }
            *(float2*)(C + i0) = v0;
            *(float2*)(C + i1) = v1;
        }
    }
}

__global__ __launch_bounds__(256) void moe_gemm_kernel(
    const u16* __restrict__ Ah_g, const u16* __restrict__ Al_g,
    const u16* __restrict__ Wh, const u16* __restrict__ Wl,
    float* __restrict__ C, int N, int K, long long Wstride)
{
    extern __shared__ uint32_t S[];
    const int bt = blockIdx.y;
    const int e = g_tileExp[bt];
    if (e < 0) return;
    const int rowbase = g_tileBase[bt];
    const int mvalid  = g_tileRows[bt];
    const u16* Bh_g = Wh + (long long)e * Wstride;
    const u16* Bl_g = Wl + (long long)e * Wstride;

    const int bn = blockIdx.x;
    const int t = threadIdx.x;
    const int lane = t & 31, wid = t >> 5;
    const int gid = lane >> 2, tig = lane & 3;
    const int wm = wid >> 1, wn = wid & 1;
    const int rA = t >> 1, hA = t & 1;
    const int rAc = (rA < mvalid) ? rA : (mvalid - 1);

    const u16* Agh = Ah_g + (long long)(rowbase + rAc) * K + hA*16;
    const u16* Agl = Al_g + (long long)(rowbase + rAc) * K + hA*16;
    const u16* Bgh = Bh_g + (long long)(bn*128 + rA) * K + hA*16;
    const u16* Bgl = Bl_g + (long long)(bn*128 + rA) * K + hA*16;

    float acc[2][8][4];
    #pragma unroll
    for (int mt=0;mt<2;mt++)
        #pragma unroll
        for (int nt=0;nt<8;nt++)
            #pragma unroll
            for (int i=0;i<4;i++) acc[mt][nt][i]=0.f;

    TileRegs tr;
    gemm_load_tile(tr, Agh, Agl, Bgh, Bgl);
    gemm_store_tile(S, 0, rA, hA, tr);
    __syncthreads();

    int buf = 0;
    for (int k0 = 0; k0 < K; k0 += 32) {
        bool more = (k0 + 32 < K);
        if (more) gemm_load_tile(tr, Agh, Agl, Bgh, Bgl);
        gemm_compute(S, buf, wm, wn, gid, tig, acc);
        if (more) gemm_store_tile(S, buf^1, rA, hA, tr);
        buf ^= 1;
        __syncthreads();
    }

    #pragma unroll
    for (int mt=0;mt<2;mt++) {
        int rl0 = wm*32 + mt*16 + gid;
        int rl1 = rl0 + 8;
        #pragma unroll
        for (int nt=0;nt<8;nt++) {
            long long col0 = (long long)bn*128 + wn*64 + nt*8 + tig*2;
            if (rl0 < mvalid) {
                long long i0 = (long long)(rowbase + rl0)*N + col0;
                *(float2*)(C + i0) = make_float2(acc[mt][nt][0], acc[mt][nt][1]);
            }
            if (rl1 < mvalid) {
                long long i1 = (long long)(rowbase + rl1)*N + col0;
                *(float2*)(C + i1) = make_float2(acc[mt][nt][2], acc[mt][nt][3]);
            }
        }
    }
}

// ---------------- MoE routing-permutation kernels ----------------
__global__ void zero_cnt_kernel() {
    if (threadIdx.x < LE) g_cnt[threadIdx.x] = 0;
}
__global__ void assign1_kernel(const void* __restrict__ idx, long long idxOff) {
    int n = blockIdx.x*blockDim.x + threadIdx.x;
    if (n >= NTOK) return;
    #pragma unroll
    for (int k=0;k<TOPK;k++) {
        int f = n*TOPK + k;
        int e = load_expert_idx(idx, idxOff + f);
        g_exp[f] = e;
        g_pos[f] = atomicAdd(&g_cnt[e], 1);
    }
}
__global__ void scan_tiles_kernel() {
    int off = 0;
    for (int e=0;e<LE;e++) { g_off[e]=off; off += g_cnt[e]; }
    g_off[LE]=off;
    int t = 0;
    for (int e=0;e<LE;e++) {
        int c = g_cnt[e];
        for (int j=0;j<c;j+=128) {
            g_tileExp[t]=e; g_tileBase[t]=g_off[e]+j;
            g_tileRows[t]=min(128, c-j);
            t++;
        }
    }
    for (;t<MAXTILES;t++) g_tileExp[t]=-1;
}
__global__ void assign2_kernel() {
    int f = blockIdx.x*blockDim.x + threadIdx.x;
    if (f >= NASSIGN) return;
    int slot = g_off[g_exp[f]] + g_pos[f];
    g_slot[f] = slot;
    g_perm[slot] = f / TOPK;
}
__global__ void gather_kernel() {
    int slot = blockIdx.x;
    int n = g_perm[slot];
    int t = threadIdx.x;
    if (t < 128) {
        const uint4* src = (const uint4*)(g_sxnh + (long long)n*DIM);
        uint4* dst = (uint4*)(g_sxph + (long long)slot*DIM);
        dst[t] = src[t];
    } else {
        const uint4* src = (const uint4*)(g_sxnl + (long long)n*DIM);
        uint4* dst = (uint4*)(g_sxpl + (long long)slot*DIM);
        dst[t-128] = src[t-128];
    }
}
__global__ void combine2_kernel(float* __restrict__ xout, const float* __restrict__ yp,
                                const float* __restrict__ sc) {
    long long i = (long long)blockIdx.x*256 + threadIdx.x;
    int n = (int)(i >> 10);
    #pragma unroll
    for (int k=0;k<TOPK;k++){
        int f = n*TOPK + k;
        xout[i] += sc[f] * yp[(long long)g_slot[f]*DIM + (int)(i & 1023)];
    }
}

// ---------------- RMSNorm (fused split output) ----------------
__global__ void rmsnorm_kernel(const float* __restrict__ x, const float* __restrict__ g,
                               float* __restrict__ o) {
    int n = blockIdx.x, tid = threadIdx.x;
    const float* xr = x + (long long)n*DIM;
    float s = 0.f;
    for (int d=tid; d<DIM; d+=256){ float v=xr[d]; s += v*v; }
    __shared__ float red[256];
    red[tid]=s; __syncthreads();
    for (int st=128; st>0; st>>=1){ if(tid<st) red[tid]+=red[tid+st]; __syncthreads(); }
    float scale = rsqrtf(red[0]/(float)DIM + 1e-6f);
    float* orow = o + (long long)n*DIM;
    u16* hrow = g_sxnh + (long long)n*DIM;
    u16* lrow = g_sxnl + (long long)n*DIM;
    for (int d=tid; d<DIM; d+=256) {
        float v = xr[d]*scale*g[d];
        orow[d] = v;
        u16 h,l; split1(v,h,l);
        hrow[d]=h; lrow[d]=l;
    }
}

// ---------------- RoPE ----------------
__global__ void rope_kernel(float* __restrict__ qkv) {
    int s = blockIdx.x;
    int t = threadIdx.x;
    int isK = t >> 9;
    int p = t & 511;
    int h = p >> 5;
    int j = p & 31;
    float* base = qkv + (long long)s*3*DIM + isK*DIM + h*HEADD;
    float inv = powf(10000.0f, -(float)j/32.0f);
    float ang = (float)s * inv;
    float sn, c; sincosf(ang, &sn, &c);
    float x1 = base[j], x2 = base[j+32];
    base[j]    =  x1*c + x2*sn;
    base[j+32] = -x1*sn + x2*c;
}

// ---------------- flash-style attention (doc-skip + fused split output) ----------------
__global__ __launch_bounds__(64) void attn_kernel(const float* __restrict__ qkv,
                                                  const int* __restrict__ doc) {
    int h  = blockIdx.y;
    int qt = blockIdx.x;
    int tid = threadIdx.x;
    int qg = qt*64 + tid;
    __shared__ float Ks[64][68];
    __shared__ float Vs[64][68];
    __shared__ int docs[64];
    float q[64], acc[64];
    const float* qp = qkv + (long long)qg*3*DIM + h*HEADD;
    #pragma unroll
    for (int d=0; d<64; d+=4) {
        float4 v = *(const float4*)(qp + d);
        q[d]=v.x; q[d+1]=v.y; q[d+2]=v.z; q[d+3]=v.w;
    }
    #pragma unroll
    for (int d=0; d<64; d++) acc[d]=0.f;
    int dq = doc[qg];
    float m = -1e30f, l = 0.f;

    int ktb = g_ds[qt*64] >> 6;
    for (int kt=ktb; kt<=qt; kt++) {
        const float* kp = qkv + (long long)(kt*64+tid)*3*DIM + DIM + h*HEADD;
        const float* vp = kp + DIM;
        #pragma unroll
        for (int d=0; d<64; d+=4) {
            *(float4*)&Ks[tid][d] = *(const float4*)(kp+d);
            *(float4*)&Vs[tid][d] = *(const float4*)(vp+d);
        }
        docs[tid] = doc[kt*64+tid];
        __syncthreads();
        int jmax = min(64, qg - kt*64 + 1);
        for (int j=0; j<jmax; j++) {
            if (docs[j] == dq) {
                float s0=0,s1=0,s2=0,s3=0;
                #pragma unroll
                for (int d=0; d<64; d+=4) {
                    float4 kv = *(const float4*)&Ks[j][d];
                    s0 += q[d]  *kv.x; s1 += q[d+1]*kv.y;
                    s2 += q[d+2]*kv.z; s3 += q[d+3]*kv.w;
                }
                float s = ((s0+s1)+(s2+s3))*0.125f;
                float mn  = fmaxf(m, s);
                float corr = __expf(m - mn);
                float pexp = __expf(s - mn);
                l = l*corr + pexp;
                #pragma unroll
                for (int d=0; d<64; d+=4) {
                    float4 vv = *(const float4*)&Vs[j][d];
                    acc[d]   = acc[d]  *corr + pexp*vv.x;
                    acc[d+1] = acc[d+1]*corr + pexp*vv.y;
                    acc[d+2] = acc[d+2]*corr + pexp*vv.z;
                    acc[d+3] = acc[d+3]*corr + pexp*vv.w;
                }
                m = mn;
            }
        }
        __syncthreads();
    }
    float inv = 1.0f / l;
    u16 oh[64], ol[64];
    #pragma unroll
    for (int d=0; d<64; d++) split1(acc[d]*inv, oh[d], ol[d]);
    u16* ph = g_satth + (long long)qg*DIM + h*HEADD;
    u16* pl = g_sattl + (long long)qg*DIM + h*HEADD;
    #pragma unroll
    for (int d=0; d<64; d+=8) {
        *(uint4*)(ph + d) = *(uint4*)(oh + d);
        *(uint4*)(pl + d) = *(uint4*)(ol + d);
    }
}

// ---------------- SwiGLU ----------------
__global__ void swiglu_kernel(const float* __restrict__ u, u16* __restrict__ hh,
                              u16* __restrict__ hl, int H) {
    long long i = (long long)blockIdx.x*256 + threadIdx.x;
    long long n = i / H; int c = (int)(i % H);
    float a = u[n*2*H + c];
    float b = u[n*2*H + H + c];
    float r = (a / (1.f + __expf(-a))) * b;
    u16 h,l; split1(r,h,l);
    hh[i]=h; hl[i]=l;
}

__global__ void swiglu2_kernel(const float* __restrict__ h1, const float* __restrict__ h2,
                               u16* __restrict__ hh, u16* __restrict__ hl) {
    long long i = (long long)blockIdx.x*256 + threadIdx.x;
    float a = h1[i];
    float r = (a / (1.f + __expf(-a))) * h2[i];
    u16 h,l; split1(r,h,l);
    hh[i]=h; hl[i]=l;
}

// ---------------- router ----------------
__global__ void router_tv_kernel(const float* __restrict__ xf, const float* __restrict__ tk,
                                 float* __restrict__ tv) {
    int n = blockIdx.x, tid = threadIdx.x;
    float p[LE];
    #pragma unroll
    for (int e=0;e<LE;e++) p[e]=0.f;
    const float* xr = xf + (long long)n*DIM;
    for (int d=tid; d<DIM; d+=256) {
        float x = xr[d];
        const float* tkr = tk + (long long)d*LE;
        #pragma unroll
        for (int e=0;e<LE;e++) p[e] += x*tkr[e];
    }
    __shared__ float red[LE][256];
    #pragma unroll
    for (int e=0;e<LE;e++) red[e][tid]=p[e];
    __syncthreads();
    for (int st=128; st>0; st>>=1) {
        if (tid < st) {
            #pragma unroll
            for (int e=0;e<LE;e++) red[e][tid]+=red[e][tid+st];
        }
        __syncthreads();
    }
    if (tid < LE) tv[(long long)n*LE + tid] = red[tid][0];
}

__global__ void router_score_kernel(const float* __restrict__ tv, const void* __restrict__ idx,
                                    long long idxOff,
                                    const float* __restrict__ vals, const float* __restrict__ rb,
                                    float* __restrict__ sc) {
    int n = blockIdx.x*blockDim.x + threadIdx.x;
    if (n >= NTOK) return;
    float s[TOPK];
    #pragma unroll
    for (int k=0;k<TOPK;k++){
        int e = load_expert_idx(idx, idxOff + (long long)n*TOPK + k);
        float v = vals[(long long)n*TOPK+k] + tv[(long long)n*LE+e] + rb[e];
        s[k] = 1.f/(1.f+__expf(-v));
    }
    float inv = 1.f/(s[0]+s[1]);
    sc[(long long)n*TOPK+0] = s[0]*inv;
    sc[(long long)n*TOPK+1] = s[1]*inv;
}

// ---------------- host ----------------
extern "C" void kernel_launch(void* const* d_in, const int* in_sizes, int n_in,
                              void* d_out, int out_size) {
    const float* x       = (const float*)d_in[0];
    const int*   doc     = (const int*)d_in[1];
    const void*  indices = d_in[2];
    const float* values  = (const float*)d_in[3];
    const float* daw = (const float*)d_in[4];
    const float* dao = (const float*)d_in[5];
    const float* dup = (const float*)d_in[6];
    const float* ddn = (const float*)d_in[7];
    const float* dag = (const float*)d_in[8];
    const float* dfg = (const float*)d_in[9];
    const float* maw = (const float*)d_in[10];
    const float* mao = (const float*)d_in[11];
    const float* mag = (const float*)d_in[12];
    const float* mfg = (const float*)d_in[13];
    const float* mex = (const float*)d_in[14];
    const float* mtk = (const float*)d_in[15];
    const float* mrb = (const float*)d_in[16];
    const float* msup= (const float*)d_in[17];
    const float* msdn= (const float*)d_in[18];
    float* out = (float*)d_out;

    void* p;
    cudaGetSymbolAddress(&p, g_wh);    u16* WH = (u16*)p;
    cudaGetSymbolAddress(&p, g_wl);    u16* WL = (u16*)p;
    cudaGetSymbolAddress(&p, g_sxnh);  u16* SXNH=(u16*)p;
    cudaGetSymbolAddress(&p, g_sxnl);  u16* SXNL=(u16*)p;
    cudaGetSymbolAddress(&p, g_satth); u16* SATTH=(u16*)p;
    cudaGetSymbolAddress(&p, g_sattl); u16* SATTL=(u16*)p;
    cudaGetSymbolAddress(&p, g_shh);   u16* SHH=(u16*)p;
    cudaGetSymbolAddress(&p, g_shl);   u16* SHL=(u16*)p;
    cudaGetSymbolAddress(&p, g_sxph);  u16* SXPH=(u16*)p;
    cudaGetSymbolAddress(&p, g_sxpl);  u16* SXPL=(u16*)p;
    cudaGetSymbolAddress(&p, g_shsh);  u16* SHSH=(u16*)p;
    cudaGetSymbolAddress(&p, g_shsl);  u16* SHSL=(u16*)p;
    cudaGetSymbolAddress(&p, g_xn);   float* XN  = (float*)p;
    cudaGetSymbolAddress(&p, g_qkv);  float* QKV = (float*)p;
    cudaGetSymbolAddress(&p, g_xi);   float* XI  = (float*)p;
    cudaGetSymbolAddress(&p, g_u);    float* U   = (float*)p;
    cudaGetSymbolAddress(&p, g_h1);   float* H1  = (float*)p;
    cudaGetSymbolAddress(&p, g_h2);   float* H2  = (float*)p;
    cudaGetSymbolAddress(&p, g_yp);   float* YP  = (float*)p;
    cudaGetSymbolAddress(&p, g_tv);   float* TV  = (float*)p;
    cudaGetSymbolAddress(&p, g_sc);   float* SC  = (float*)p;
    cudaGetSymbolAddress(&p, g_xa);   float* XA  = (float*)p;
    cudaGetSymbolAddress(&p, g_xb);   float* XB  = (float*)p;

    static cudaStream_t sW = nullptr, sE = nullptr;
    static cudaEvent_t evFork, evW1, evW2, evW3, evMF[2], evMJ[2];
    if (!sW) {
        cudaStreamCreateWithFlags(&sW, cudaStreamNonBlocking);
        cudaStreamCreateWithFlags(&sE, cudaStreamNonBlocking);
        cudaEventCreateWithFlags(&evFork, cudaEventDisableTiming);
        cudaEventCreateWithFlags(&evW1, cudaEventDisableTiming);
        cudaEventCreateWithFlags(&evW2, cudaEventDisableTiming);
        cudaEventCreateWithFlags(&evW3, cudaEventDisableTiming);
        for (int i=0;i<2;i++) {
            cudaEventCreateWithFlags(&evMF[i], cudaEventDisableTiming);
            cudaEventCreateWithFlags(&evMJ[i], cudaEventDisableTiming);
        }
        cudaFuncSetAttribute(bf16gemm_kernel, cudaFuncAttributeMaxDynamicSharedMemorySize, SMEM_BYTES);
        cudaFuncSetAttribute(moe_gemm_kernel, cudaFuncAttributeMaxDynamicSharedMemorySize, SMEM_BYTES);
    }

    detect_idx_kernel<<<1,1>>>(indices);
    docstart_kernel<<<(NTOK+255)/256,256>>>(doc);

    // ---- fork weight-conversion stream ----
    cudaEventRecord(evFork, 0);
    cudaStreamWaitEvent(sW, evFork, 0);

    auto convT = [&](const float* src, long long off, int K, int N, int batch, long long sSrc){
        wconvT_kernel<<<dim3(N/32, K/32, batch),256,0,sW>>>(src, WH+off, WL+off, K, N, sSrc, (long long)K*N);
    };
    // stage 1: dense attention weights (needed first)
    convT(daw, OFF_DAW, 1024, 3072, 2, 3072LL*1024);
    convT(dao, OFF_DAO, 1024, 1024, 2, 1024LL*1024);
    cudaEventRecord(evW1, sW);
    // stage 2: dense FFN weights
    convT(dup, OFF_DUP, 1024, 8192, 2, 8192LL*1024);
    convT(ddn, OFF_DDN, 4096, 1024, 2, 1024LL*4096);
    cudaEventRecord(evW2, sW);
    // stage 3: MoE weights
    convT(maw, OFF_MAW, 1024, 3072, 2, 3072LL*1024);
    convT(mao, OFF_MAO, 1024, 1024, 2, 1024LL*1024);
    for (int i=0;i<2;i++) {
        const float* W1 = mex + ((long long)i*3+0)*LE*DIM*DIME;
        const float* W2 = mex + ((long long)i*3+1)*LE*DIM*DIME;
        const float* W3 = mex + ((long long)i*3+2)*LE*DIM*DIME;
        convT(W1, OFF_W1 + (long long)i*LE*DIM*DIME, 1024, 512, 8, (long long)DIM*DIME);
        convT(W2, OFF_W2 + (long long)i*LE*DIM*DIME, 1024, 512, 8, (long long)DIM*DIME);
        wconv_kernel<<<(LE*DIM*DIME)/256,256,0,sW>>>(W3, WH + OFF_W3 + (long long)i*LE*DIM*DIME,
                                                     WL + OFF_W3 + (long long)i*LE*DIM*DIME);
    }
    convT(msup, OFF_MSUP, 1024, 2048, 2, 2048LL*1024);
    convT(msdn, OFF_MSDN, 1024, 1024, 2, 1024LL*1024);
    cudaEventRecord(evW3, sW);

    auto gemmS = [&](cudaStream_t st, const u16* Ah, const u16* Al, long long woff, float* C,
                     int M, int N, int K, const float* R){
        bf16gemm_kernel<<<dim3(N/128, M/128), 256, SMEM_BYTES, st>>>(Ah, Al, WH+woff, WL+woff, C, R, M, N, K);
    };
    auto gemm = [&](const u16* Ah, const u16* Al, long long woff, float* C,
                    int M, int N, int K, const float* R){
        gemmS(0, Ah, Al, woff, C, M, N, K, R);
    };

    auto attn_block = [&](const float* xin, long long awoff, long long aooff, const float* ag){
        rmsnorm_kernel<<<NTOK,256>>>(xin, ag, XN);
        gemm(SXNH, SXNL, awoff, QKV, NTOK, 3*DIM, DIM, nullptr);
        rope_kernel<<<NTOK,1024>>>(QKV);
        attn_kernel<<<dim3(NTOK/64, HEADS),64>>>(QKV, doc);
        gemm(SATTH, SATTL, aooff, XI, NTOK, DIM, DIM, xin);
    };

    auto dense = [&](const float* xin, float* xout, int l){
        if (l == 0) cudaStreamWaitEvent(0, evW1, 0);
        attn_block(xin, OFF_DAW + (long long)l*3072*1024, OFF_DAO + (long long)l*1024*1024,
                   dag + (long long)l*DIM);
        rmsnorm_kernel<<<NTOK,256>>>(XI, dfg + (long long)l*DIM, XN);
        if (l == 0) cudaStreamWaitEvent(0, evW2, 0);
        gemm(SXNH, SXNL, OFF_DUP + (long long)l*8192*1024, U, NTOK, 2*FFNH, DIM, nullptr);
        swiglu_kernel<<<(NTOK*FFNH)/256,256>>>(U, SHH, SHL, FFNH);
        gemm(SHH, SHL, OFF_DDN + (long long)l*1024*4096, xout, NTOK, DIM, FFNH, XI);
    };

    auto moe = [&](const float* xin, float* xout, int i){
        if (i == 0) cudaStreamWaitEvent(0, evW3, 0);
        attn_block(xin, OFF_MAW + (long long)i*3072*1024, OFF_MAO + (long long)i*1024*1024,
                   mag + (long long)i*DIM);
        rmsnorm_kernel<<<NTOK,256>>>(XI, mfg + (long long)i*DIM, XN);
        long long idxOff = (long long)i*NTOK*TOPK;

        // ---- fork shared-expert chain onto sE ----
        cudaEventRecord(evMF[i], 0);
        cudaStreamWaitEvent(sE, evMF[i], 0);
        gemmS(sE, SXNH, SXNL, OFF_MSUP + (long long)i*2048*1024, U, NTOK, 2*DIMS, DIM, nullptr);
        swiglu_kernel<<<(NTOK*DIMS)/256,256,0,sE>>>(U, SHH, SHL, DIMS);
        gemmS(sE, SHH, SHL, OFF_MSDN + (long long)i*1024*1024, xout, NTOK, DIM, DIMS, XI);
        cudaEventRecord(evMJ[i], sE);

        // ---- routed-expert chain on main stream ----
        router_tv_kernel<<<NTOK,256>>>(XN, mtk + (long long)i*DIM*LE, TV);
        router_score_kernel<<<(NTOK+255)/256,256>>>(TV, indices, idxOff,
                                                    values + idxOff,
                                                    mrb + (long long)i*LE, SC);
        zero_cnt_kernel<<<1,32>>>();
        assign1_kernel<<<(NTOK+255)/256,256>>>(indices, idxOff);
        scan_tiles_kernel<<<1,1>>>();
        assign2_kernel<<<(NASSIGN+255)/256,256>>>();
        gather_kernel<<<NASSIGN,256>>>();

        long long w1o = OFF_W1 + (long long)i*LE*DIM*DIME;
        long long w2o = OFF_W2 + (long long)i*LE*DIM*DIME;
        long long w3o = OFF_W3 + (long long)i*LE*DIM*DIME;
        moe_gemm_kernel<<<dim3(DIME/128, MAXTILES), 256, SMEM_BYTES>>>(SXPH, SXPL, WH+w1o, WL+w1o, H1,
                                                           DIME, DIM, (long long)DIM*DIME);
        moe_gemm_kernel<<<dim3(DIME/128, MAXTILES), 256, SMEM_BYTES>>>(SXPH, SXPL, WH+w2o, WL+w2o, H2,
                                                           DIME, DIM, (long long)DIM*DIME);
        swiglu2_kernel<<<((long long)NASSIGN*DIME)/256,256>>>(H1, H2, SHSH, SHSL);
        moe_gemm_kernel<<<dim3(DIM/128, MAXTILES), 256, SMEM_BYTES>>>(SHSH, SHSL, WH+w3o, WL+w3o, YP,
                                                          DIM, DIME, (long long)DIM*DIME);

        // ---- join shared-expert chain, then combine ----
        cudaStreamWaitEvent(0, evMJ[i], 0);
        combine2_kernel<<<(NTOK*DIM)/256,256>>>(xout, YP, SC);
    };

    dense(x,  XA, 0);
    moe  (XA, XB, 0);
    moe  (XB, XA, 1);
    dense(XA, out, 1);
}